// round 1
// baseline (speedup 1.0000x reference)
#include <cuda_runtime.h>
#include <cuda_bf16.h>

// kspaceMap: out (32,129,128,128) f32.
//   channels 0..127:  sep[b,w,h,w'] = (Re(t)·cos(2πww'/W) − Im(t)·sin(2πww'/W)) / W
//                     with t[b,h,w] = FFT_W(input[b,0,h,:])[w]
//   channel 128:      copy of input[b,1,h,:]
// mask input is unused by the reference.

#define IM  128
#define BZ  32
#define CH_OUT 129

__global__ void __launch_bounds__(IM) kspace_kernel(const float* __restrict__ in,
                                                    float* __restrict__ out)
{
    const int bh  = blockIdx.x;      // 0 .. BZ*IM-1
    const int b   = bh >> 7;         // / IM
    const int h   = bh & (IM - 1);
    const int tid = threadIdx.x;     // 0 .. 127

    __shared__ float  xs[IM];        // input row
    __shared__ float2 cs[IM];        // (cos, sin)(2πk/IM)
    __shared__ float2 tw[IM];        // (Re, Im) of DFT / IM

    // Load x row (channel 0) and fuse the channel-1 passthrough copy.
    const unsigned in_row0 = ((unsigned)(b * 2 + 0) * IM + h) * IM;
    const unsigned in_row1 = ((unsigned)(b * 2 + 1) * IM + h) * IM;
    xs[tid] = in[in_row0 + tid];
    out[(((unsigned)b * CH_OUT + IM) * IM + h) * IM + tid] = in[in_row1 + tid];

    // cos/sin table: cs[k] = (cos(2πk/IM), sin(2πk/IM))
    {
        float s, c;
        sincospif(2.0f * (float)tid / (float)IM, &s, &c);
        cs[tid] = make_float2(c, s);
    }
    __syncthreads();

    // DFT bin w = tid:  t_w = sum_u x[u] * e^{-2πi·u·w/IM}
    {
        float re = 0.0f, im = 0.0f;
        int idx = 0;                       // (u*tid) mod IM, running
        #pragma unroll 8
        for (int u = 0; u < IM; ++u) {
            const float2 e  = cs[idx];
            const float  xv = xs[u];
            re = fmaf(xv,  e.x, re);
            im = fmaf(xv, -e.y, im);
            idx = (idx + tid) & (IM - 1);
        }
        const float inv = 1.0f / (float)IM;
        tw[tid] = make_float2(re * inv, im * inv);
    }
    __syncthreads();

    // Output: thread = w' (contiguous across warp -> coalesced stores), loop w.
    // out[((b*129 + w)*IM + h)*IM + w']
    {
        const unsigned base = (((unsigned)b * CH_OUT) * IM + h) * IM + tid;
        int idx = 0;                       // (w*tid) mod IM, running
        #pragma unroll 8
        for (int w = 0; w < IM; ++w) {
            const float2 t = tw[w];        // broadcast
            const float2 e = cs[idx];
            out[base + (unsigned)w * (IM * IM)] = t.x * e.x - t.y * e.y;
            idx = (idx + tid) & (IM - 1);
        }
    }
}

extern "C" void kernel_launch(void* const* d_in, const int* in_sizes, int n_in,
                              void* d_out, int out_size)
{
    const float* in  = (const float*)d_in[0];   // (32,2,128,128) f32
    float*       out = (float*)d_out;           // (32,129,128,128) f32
    (void)in_sizes; (void)n_in; (void)out_size;

    kspace_kernel<<<BZ * IM, IM>>>(in, out);
}

// round 2
// speedup vs baseline: 1.8402x; 1.8402x over previous
#include <cuda_runtime.h>
#include <cuda_bf16.h>

// kspaceMap: out (32,129,128,128) f32.
//   channels 0..127:  sep[b,w,h,w'] = (Re(t)·cos(2πww'/W) − Im(t)·sin(2πww'/W)) / W
//                     with t[b,h,w] = FFT_W(input[b,0,h,:])[w]
//   channel 128:      copy of input[b,1,h,:]
// mask input is unused by the reference.
//
// R2: no twiddle table in shared (R1 had 4-16 way bank conflicts on it).
// All twiddles come from register rotation recurrences with exact sincospif
// steps. Stores vectorized to float4 (lane = 4 consecutive w', warp strides w).

#define IM  128
#define BZ  32
#define CH_OUT 129

__global__ void __launch_bounds__(IM) kspace_kernel(const float* __restrict__ in,
                                                    float* __restrict__ out)
{
    const int bh  = blockIdx.x;      // 0 .. BZ*IM-1
    const int b   = bh >> 7;
    const int h   = bh & (IM - 1);
    const int tid = threadIdx.x;     // 0 .. 127

    __shared__ float  xs[IM];        // input row (broadcast reads only)
    __shared__ float2 tw[IM];        // (Re, Im) of DFT / IM (broadcast reads only)

    // Load x row (channel 0) and fuse the channel-1 passthrough copy.
    const unsigned in_row0 = (((unsigned)b * 2 + 0) * IM + h) * IM;
    const unsigned in_row1 = (((unsigned)b * 2 + 1) * IM + h) * IM;
    xs[tid] = in[in_row0 + tid];
    out[(((unsigned)b * CH_OUT + IM) * IM + h) * IM + tid] = in[in_row1 + tid];
    __syncthreads();

    // ---- DFT bin w = tid:  t_w = sum_u x[u] * e^{-2πi·u·w/IM} ----
    // Twiddle via rotation recurrence: (c,s) = (cos uθ, sin uθ), θ = 2π·tid/IM.
    {
        float S, C;
        sincospif(2.0f * (float)tid * (1.0f / IM), &S, &C);
        float c = 1.0f, s = 0.0f, re = 0.0f, im = 0.0f;
        #pragma unroll 8
        for (int u = 0; u < IM; ++u) {
            const float xv = xs[u];                 // LDS broadcast, conflict-free
            re = fmaf(xv,  c, re);
            im = fmaf(xv, -s, im);
            const float cn = fmaf(c, C, -(s * S));  // rotate by θ
            s = fmaf(s, C, c * S);
            c = cn;
        }
        const float inv = 1.0f / (float)IM;
        tw[tid] = make_float2(re * inv, im * inv);
    }
    __syncthreads();

    // ---- Output: out[((b*129 + w)*IM + h)*IM + w'] ----
    // lane l owns w' = 4l..4l+3 (float4 store); warp j walks w = j, j+4, ...
    // Twiddle e^{-i·w·w'·2π/IM} per w' via rotation with step 4θ_{w'}.
    {
        const int warp = tid >> 5;
        const int lane = tid & 31;

        float c0[4], s0[4], Cs[4], Ss[4];
        #pragma unroll
        for (int k = 0; k < 4; ++k) {
            // θ_{w'}/π with w' = 4*lane + k :  (2·w')/IM = w'/64
            const float th_over_pi = (float)(4 * lane + k) * (1.0f / 64.0f);
            sincospif(4.0f * th_over_pi, &Ss[k], &Cs[k]);            // step = 4θ
            sincospif((float)warp * th_over_pi, &s0[k], &c0[k]);     // start w=warp
        }

        const unsigned base = (((unsigned)b * CH_OUT + warp) * IM + h) * IM
                              + (unsigned)(4 * lane);
        #pragma unroll 4
        for (int t = 0; t < 32; ++t) {
            const int    w  = warp + 4 * t;
            const float2 tt = tw[w];                // LDS broadcast, conflict-free
            float4 v;
            v.x = tt.x * c0[0] - tt.y * s0[0];
            v.y = tt.x * c0[1] - tt.y * s0[1];
            v.z = tt.x * c0[2] - tt.y * s0[2];
            v.w = tt.x * c0[3] - tt.y * s0[3];
            *(float4*)(out + base + (unsigned)t * (4u * IM * IM)) = v;
            #pragma unroll
            for (int k = 0; k < 4; ++k) {           // rotate by 4θ_k
                const float cn = fmaf(c0[k], Cs[k], -(s0[k] * Ss[k]));
                s0[k] = fmaf(s0[k], Cs[k], c0[k] * Ss[k]);
                c0[k] = cn;
            }
        }
    }
}

extern "C" void kernel_launch(void* const* d_in, const int* in_sizes, int n_in,
                              void* d_out, int out_size)
{
    const float* in  = (const float*)d_in[0];   // (32,2,128,128) f32
    float*       out = (float*)d_out;           // (32,129,128,128) f32
    (void)in_sizes; (void)n_in; (void)out_size;

    kspace_kernel<<<BZ * IM, IM>>>(in, out);
}